// round 12
// baseline (speedup 1.0000x reference)
#include <cuda_runtime.h>
#include <cuda_fp16.h>
#include <cstdint>

// Problem:
//   x:      (B=4, T=4096, D=1024) f32
//   idx:    (B=4, E=8, C=1024)    i32
//   weight: (E=8, O=512, D=1024)  f32
//   bias:   (E=8, O=512)          f32
//   out:    (B=4, E=8, C=1024, O=512) f32
// out[b,e,c,o] = sum_d x[b, idx[b,e,c], d] * w[e,o,d] + bias[e,o]
//
// fp16 HMMA GEMM. EXPERIMENT: f16 accumulation within each K=64 chunk
// (possible 2x HMMA rate vs f32-accum), promoted to f32 master accumulators
// once per chunk. 4-stage cp.async pipeline, 1 CTA/SM, 8 warps (2M x 4N),
// warp tile 64x32.

#define B_ 4
#define T_ 4096
#define D_ 1024
#define E_ 8
#define C_ 1024
#define O_ 512

#define MT 128
#define NT 128
#define KC 64             // fp16 k per chunk -> 128B rows
#define NCHUNK (D_ / KC)  // 16
#define STAGES 4
#define STAGE_SZ 32768    // A 16K + W 16K
#define SMEM_TOTAL (STAGES * STAGE_SZ)   // 131072

__device__ __half g_x16[B_ * T_ * D_];
__device__ __half g_w16[E_ * O_ * D_];

#define NXG ((B_ * T_ * D_) / 8)
#define NWG ((E_ * O_ * D_) / 8)

__device__ __forceinline__ uint32_t smem_u32(const void* p) {
    uint32_t a;
    asm("{ .reg .u64 t; cvta.to.shared.u64 t, %1; cvt.u32.u64 %0, t; }" : "=r"(a) : "l"(p));
    return a;
}
__device__ __forceinline__ void cp_async16(uint32_t dst, const void* src) {
    asm volatile("cp.async.cg.shared.global [%0], [%1], 16;" :: "r"(dst), "l"(src));
}
__device__ __forceinline__ void cp_commit() {
    asm volatile("cp.async.commit_group;" ::: "memory");
}
__device__ __forceinline__ void cp_wait2() {
    asm volatile("cp.async.wait_group 2;" ::: "memory");
}
__device__ __forceinline__ void ldsm_x4(uint32_t* r, uint32_t addr) {
    asm volatile("ldmatrix.sync.aligned.m8n8.x4.shared.b16 {%0,%1,%2,%3}, [%4];"
                 : "=r"(r[0]), "=r"(r[1]), "=r"(r[2]), "=r"(r[3]) : "r"(addr));
}
// f16-accumulate MMA, in-place D=C
__device__ __forceinline__ void mma_h16(uint32_t* d, const uint32_t* a, uint32_t b0, uint32_t b1) {
    asm volatile(
        "mma.sync.aligned.m16n8k16.row.col.f16.f16.f16.f16 "
        "{%0,%1}, {%2,%3,%4,%5}, {%6,%7}, {%0,%1};"
        : "+r"(d[0]), "+r"(d[1])
        : "r"(a[0]), "r"(a[1]), "r"(a[2]), "r"(a[3]), "r"(b0), "r"(b1));
}
// f16-accumulate MMA, init form: D = A*B + 0
__device__ __forceinline__ void mma_h16_init(uint32_t* d, const uint32_t* a, uint32_t b0, uint32_t b1, uint32_t z) {
    asm volatile(
        "mma.sync.aligned.m16n8k16.row.col.f16.f16.f16.f16 "
        "{%0,%1}, {%2,%3,%4,%5}, {%6,%7}, {%8,%8};"
        : "=r"(d[0]), "=r"(d[1])
        : "r"(a[0]), "r"(a[1]), "r"(a[2]), "r"(a[3]), "r"(b0), "r"(b1), "r"(z));
}

// ---------------------------------------------------------------------------
// merged fp32 -> fp16 converter for x and w
// ---------------------------------------------------------------------------
__global__ __launch_bounds__(256)
void convert_all_kernel(const float* __restrict__ x, const float* __restrict__ w) {
    const size_t g = (size_t)blockIdx.x * 256 + threadIdx.x;
    const float* src;
    __half* dst;
    size_t i;
    if (g < NXG) { i = g * 8;          src = x + i; dst = g_x16 + i; }
    else         { i = (g - NXG) * 8;  src = w + i; dst = g_w16 + i; }
    float4 v0 = *(const float4*)(src);
    float4 v1 = *(const float4*)(src + 4);
    __half2 h0 = __floats2half2_rn(v0.x, v0.y);
    __half2 h1 = __floats2half2_rn(v0.z, v0.w);
    __half2 h2 = __floats2half2_rn(v1.x, v1.y);
    __half2 h3 = __floats2half2_rn(v1.z, v1.w);
    *reinterpret_cast<uint4*>(dst) =
        make_uint4(*(uint32_t*)&h0, *(uint32_t*)&h1, *(uint32_t*)&h2, *(uint32_t*)&h3);
}

// ---------------------------------------------------------------------------
// Main GEMM: 256 threads, 8 warps 2(M)x4(N), warp tile 64x32, 4-stage cp.async
// ---------------------------------------------------------------------------
__global__ __launch_bounds__(256, 1)
void moe_fp16_kernel(const int*   __restrict__ idx,
                     const float* __restrict__ bias,
                     float*       __restrict__ out)
{
    extern __shared__ char smem[];
    const uint32_t sb = smem_u32(smem);
    const int tid  = threadIdx.x;
    const int wid  = tid >> 5;
    const int lane = tid & 31;

    const int be = blockIdx.z;
    const int b  = be >> 3;
    const int e  = be & 7;
    const int c0 = blockIdx.y * MT;
    const int o0 = blockIdx.x * NT;

    // ---- producer mapping: row = tid/2, 64B half = tid&1; 4x16B per operand ----
    const int prow  = tid >> 1;
    const int phalf = (tid & 1) * 64;
    const int tok   = idx[be * C_ + c0 + prow];
    const __half* asrc = g_x16 + ((size_t)b * T_ + tok) * D_ + (phalf >> 1);
    const __half* wsrc = g_w16 + ((size_t)(e * O_ + o0 + prow)) * D_ + (phalf >> 1);
    const uint32_t pXor  = (uint32_t)((prow & 7) << 4);
    const uint32_t pRowB = (uint32_t)(prow * 128);

    // ---- compute mapping ----
    const int wm = wid >> 2;                       // 0..1 -> M offset wm*64
    const int wn = wid & 3;                        // 0..3 -> N offset wn*32

    const uint32_t fXor = (uint32_t)((lane & 7) << 4);
    const uint32_t aBase = (uint32_t)((wm * 64 + (lane & 15)) * 128);
    const uint32_t aSegL = (uint32_t)((lane >> 4) * 16);
    const uint32_t wBase = (uint32_t)(16384 + (wn * 32 + ((lane >> 4) << 3) + (lane & 7)) * 128);
    const uint32_t wSegL = (uint32_t)(((lane >> 3) & 1) * 16);

    float acc[4][4][4];
    #pragma unroll
    for (int i = 0; i < 4; i++)
        #pragma unroll
        for (int j = 0; j < 4; j++)
            #pragma unroll
            for (int q = 0; q < 4; q++) acc[i][j][q] = 0.0f;

    auto load_stage = [&](int st, int kc) {
        const uint32_t abase = sb + st * STAGE_SZ + pRowB;
        const uint32_t wbase = abase + 16384;
        const __half* ap = asrc + kc * KC;
        const __half* wp = wsrc + kc * KC;
        #pragma unroll
        for (int j = 0; j < 4; j++) {
            const uint32_t off = ((uint32_t)(phalf + j * 16)) ^ pXor;
            cp_async16(abase + off, ap + j * 8);
            cp_async16(wbase + off, wp + j * 8);
        }
    };

    load_stage(0, 0); cp_commit();
    load_stage(1, 1); cp_commit();
    load_stage(2, 2); cp_commit();

    uint32_t af[2][4][4];   // [buf][mt][frag]
    uint32_t wf[2][2][4];   // [buf][np][frag]
    const uint32_t zreg = 0;

    for (int kc = 0; kc < NCHUNK; kc++) {
        cp_wait2();
        __syncthreads();

        if (kc + 3 < NCHUNK) load_stage((kc + 3) % STAGES, kc + 3);
        cp_commit();   // empty groups at tail keep wait_group counts valid

        const uint32_t stb = sb + (kc % STAGES) * STAGE_SZ;
        const uint32_t aAddr = stb + aBase;
        const uint32_t wAddr = stb + wBase;

        // preload ks=0 fragments
        #pragma unroll
        for (int mt = 0; mt < 4; mt++)
            ldsm_x4(af[0][mt], aAddr + mt * 2048 + ((0 + aSegL) ^ fXor));
        #pragma unroll
        for (int np = 0; np < 2; np++)
            ldsm_x4(wf[0][np], wAddr + np * 2048 + ((0 + wSegL) ^ fXor));

        uint32_t d[4][4][2];  // f16x2 chunk accumulators

        #pragma unroll
        for (int ks = 0; ks < 4; ks++) {
            const int cur = ks & 1;
            const int nxt = cur ^ 1;
            if (ks < 3) {
                const uint32_t kb = (uint32_t)((ks + 1) * 32);
                #pragma unroll
                for (int mt = 0; mt < 4; mt++)
                    ldsm_x4(af[nxt][mt], aAddr + mt * 2048 + ((kb + aSegL) ^ fXor));
                #pragma unroll
                for (int np = 0; np < 2; np++)
                    ldsm_x4(wf[nxt][np], wAddr + np * 2048 + ((kb + wSegL) ^ fXor));
            }
            #pragma unroll
            for (int mt = 0; mt < 4; mt++)
                #pragma unroll
                for (int np = 0; np < 2; np++) {
                    if (ks == 0) {
                        mma_h16_init(d[mt][np * 2 + 0], af[cur][mt], wf[cur][np][0], wf[cur][np][1], zreg);
                        mma_h16_init(d[mt][np * 2 + 1], af[cur][mt], wf[cur][np][2], wf[cur][np][3], zreg);
                    } else {
                        mma_h16(d[mt][np * 2 + 0], af[cur][mt], wf[cur][np][0], wf[cur][np][1]);
                        mma_h16(d[mt][np * 2 + 1], af[cur][mt], wf[cur][np][2], wf[cur][np][3]);
                    }
                }
        }

        // promote chunk partials into f32 master accumulators
        #pragma unroll
        for (int mt = 0; mt < 4; mt++)
            #pragma unroll
            for (int n4 = 0; n4 < 4; n4++) {
                float2 p0 = __half22float2(*reinterpret_cast<__half2*>(&d[mt][n4][0]));
                float2 p1 = __half22float2(*reinterpret_cast<__half2*>(&d[mt][n4][1]));
                acc[mt][n4][0] += p0.x;
                acc[mt][n4][1] += p0.y;
                acc[mt][n4][2] += p1.x;
                acc[mt][n4][3] += p1.y;
            }
    }

    // ---- epilogue ----
    float2 bv[4];
    #pragma unroll
    for (int n4 = 0; n4 < 4; n4++)
        bv[n4] = *reinterpret_cast<const float2*>(bias + e * O_ + o0 + wn * 32 + n4 * 8 + (lane & 3) * 2);

    #pragma unroll
    for (int mt = 0; mt < 4; mt++) {
        const int row = wm * 64 + mt * 16 + (lane >> 2);
        float* d0 = out + ((size_t)be * C_ + c0 + row) * O_ + o0;
        float* d1 = d0 + 8 * O_;
        #pragma unroll
        for (int n4 = 0; n4 < 4; n4++) {
            const int col = wn * 32 + n4 * 8 + (lane & 3) * 2;
            float2 v0, v1;
            v0.x = acc[mt][n4][0] + bv[n4].x;
            v0.y = acc[mt][n4][1] + bv[n4].y;
            v1.x = acc[mt][n4][2] + bv[n4].x;
            v1.y = acc[mt][n4][3] + bv[n4].y;
            *reinterpret_cast<float2*>(d0 + col) = v0;
            *reinterpret_cast<float2*>(d1 + col) = v1;
        }
    }
}

extern "C" void kernel_launch(void* const* d_in, const int* in_sizes, int n_in,
                              void* d_out, int out_size)
{
    const float* x    = (const float*)d_in[0];
    const int*   idx  = (const int*)  d_in[1];
    const float* w    = (const float*)d_in[2];
    const float* bias = (const float*)d_in[3];
    float* out = (float*)d_out;

    cudaFuncSetAttribute(moe_fp16_kernel,
                         cudaFuncAttributeMaxDynamicSharedMemorySize, SMEM_TOTAL);

    convert_all_kernel<<<(NXG + NWG) / 256, 256>>>(x, w);

    dim3 grid(O_ / NT, C_ / MT, B_ * E_);   // (4, 8, 32)
    moe_fp16_kernel<<<grid, 256, SMEM_TOTAL>>>(idx, bias, out);
}